// round 1
// baseline (speedup 1.0000x reference)
#include <cuda_runtime.h>
#include <math.h>

#define CDIM   1024
#define NHEADS 8
#define KD     128
#define BATCH  2
#define HH     48
#define WW     48
#define NTOK   (HH*WW)        // 2304
#define MTOT   (BATCH*NTOK)   // 4608

// ---------------- scratch (static device memory; no allocations) -------------
__device__ float g_q[MTOT*CDIM];
__device__ float g_k[MTOT*CDIM];
__device__ float g_v[MTOT*CDIM];
__device__ float g_lepe[MTOT*CDIM];
__device__ float g_attn[BATCH*NHEADS*NTOK*KD];

// ---------------- GEMM: out[m,n] = (sum_k A[m,k]*W[n,k] + b[n]) * scale ------
#define GBM 128
#define GBN 128
#define GBK 8

__global__ __launch_bounds__(256,1) void gemm_qkv(
        const float* __restrict__ A,
        const float* __restrict__ W,
        const float* __restrict__ bias,
        float scale, int sel)
{
    __shared__ float As[GBK][GBM];
    __shared__ float Bs[GBK][GBN];
    float* out = (sel == 0) ? g_q : (sel == 1) ? g_k : g_v;

    const int tid = threadIdx.x;
    const int tx = tid & 15, ty = tid >> 4;
    const int bm = blockIdx.y * GBM, bn = blockIdx.x * GBN;
    const int lRow = tid >> 1, lCol = (tid & 1) * 4;

    const float* Aptr = A + (size_t)(bm + lRow) * CDIM + lCol;
    const float* Wptr = W + (size_t)(bn + lRow) * CDIM + lCol;

    float acc[8][8];
#pragma unroll
    for (int i = 0; i < 8; i++)
#pragma unroll
        for (int j = 0; j < 8; j++) acc[i][j] = 0.f;

    float4 a4 = *(const float4*)Aptr;
    float4 b4 = *(const float4*)Wptr;

    for (int kt = 0; kt < CDIM; kt += GBK) {
        As[lCol+0][lRow] = a4.x; As[lCol+1][lRow] = a4.y;
        As[lCol+2][lRow] = a4.z; As[lCol+3][lRow] = a4.w;
        Bs[lCol+0][lRow] = b4.x; Bs[lCol+1][lRow] = b4.y;
        Bs[lCol+2][lRow] = b4.z; Bs[lCol+3][lRow] = b4.w;
        __syncthreads();
        if (kt + GBK < CDIM) {
            a4 = *(const float4*)(Aptr + kt + GBK);
            b4 = *(const float4*)(Wptr + kt + GBK);
        }
#pragma unroll
        for (int k = 0; k < GBK; k++) {
            float4 x0 = *(const float4*)&As[k][ty*4];
            float4 x1 = *(const float4*)&As[k][64 + ty*4];
            float4 y0 = *(const float4*)&Bs[k][tx*4];
            float4 y1 = *(const float4*)&Bs[k][64 + tx*4];
            float xa[8] = {x0.x,x0.y,x0.z,x0.w,x1.x,x1.y,x1.z,x1.w};
            float yb[8] = {y0.x,y0.y,y0.z,y0.w,y1.x,y1.y,y1.z,y1.w};
#pragma unroll
            for (int i = 0; i < 8; i++)
#pragma unroll
                for (int j = 0; j < 8; j++)
                    acc[i][j] += xa[i] * yb[j];
        }
        __syncthreads();
    }

#pragma unroll
    for (int g = 0; g < 2; g++)
#pragma unroll
        for (int i = 0; i < 4; i++) {
            int r = bm + g*64 + ty*4 + i;
#pragma unroll
            for (int gg = 0; gg < 2; gg++) {
                int c = bn + gg*64 + tx*4;
                float4 ov;
                ov.x = (acc[g*4+i][gg*4+0] + bias[c+0]) * scale;
                ov.y = (acc[g*4+i][gg*4+1] + bias[c+1]) * scale;
                ov.z = (acc[g*4+i][gg*4+2] + bias[c+2]) * scale;
                ov.w = (acc[g*4+i][gg*4+3] + bias[c+3]) * scale;
                *(float4*)&out[(size_t)r*CDIM + c] = ov;
            }
        }
}

// A[m,k] = g_attn[b,h,n,d] + g_lepe[m,k]   (fused reorder + LePE add)
__device__ __forceinline__ float4 fused_a(int m, int k)
{
    int b = m / NTOK;
    int n = m - b * NTOK;
    int h = k >> 7;
    int d = k & 127;
    float4 at = *(const float4*)&g_attn[((((size_t)b*NHEADS)+h)*NTOK + n)*KD + d];
    float4 lp = *(const float4*)&g_lepe[(size_t)m*CDIM + k];
    return make_float4(at.x+lp.x, at.y+lp.y, at.z+lp.z, at.w+lp.w);
}

__global__ __launch_bounds__(256,1) void gemm_final(
        const float* __restrict__ W,
        const float* __restrict__ bias,
        float* __restrict__ out)
{
    __shared__ float As[GBK][GBM];
    __shared__ float Bs[GBK][GBN];

    const int tid = threadIdx.x;
    const int tx = tid & 15, ty = tid >> 4;
    const int bm = blockIdx.y * GBM, bn = blockIdx.x * GBN;
    const int lRow = tid >> 1, lCol = (tid & 1) * 4;

    const float* Wptr = W + (size_t)(bn + lRow) * CDIM + lCol;

    float acc[8][8];
#pragma unroll
    for (int i = 0; i < 8; i++)
#pragma unroll
        for (int j = 0; j < 8; j++) acc[i][j] = 0.f;

    float4 a4 = fused_a(bm + lRow, lCol);
    float4 b4 = *(const float4*)Wptr;

    for (int kt = 0; kt < CDIM; kt += GBK) {
        As[lCol+0][lRow] = a4.x; As[lCol+1][lRow] = a4.y;
        As[lCol+2][lRow] = a4.z; As[lCol+3][lRow] = a4.w;
        Bs[lCol+0][lRow] = b4.x; Bs[lCol+1][lRow] = b4.y;
        Bs[lCol+2][lRow] = b4.z; Bs[lCol+3][lRow] = b4.w;
        __syncthreads();
        if (kt + GBK < CDIM) {
            a4 = fused_a(bm + lRow, kt + GBK + lCol);
            b4 = *(const float4*)(Wptr + kt + GBK);
        }
#pragma unroll
        for (int k = 0; k < GBK; k++) {
            float4 x0 = *(const float4*)&As[k][ty*4];
            float4 x1 = *(const float4*)&As[k][64 + ty*4];
            float4 y0 = *(const float4*)&Bs[k][tx*4];
            float4 y1 = *(const float4*)&Bs[k][64 + tx*4];
            float xa[8] = {x0.x,x0.y,x0.z,x0.w,x1.x,x1.y,x1.z,x1.w};
            float yb[8] = {y0.x,y0.y,y0.z,y0.w,y1.x,y1.y,y1.z,y1.w};
#pragma unroll
            for (int i = 0; i < 8; i++)
#pragma unroll
                for (int j = 0; j < 8; j++)
                    acc[i][j] += xa[i] * yb[j];
        }
        __syncthreads();
    }

#pragma unroll
    for (int g = 0; g < 2; g++)
#pragma unroll
        for (int i = 0; i < 4; i++) {
            int r = bm + g*64 + ty*4 + i;
#pragma unroll
            for (int gg = 0; gg < 2; gg++) {
                int c = bn + gg*64 + tx*4;
                float4 ov;
                ov.x = acc[g*4+i][gg*4+0] + bias[c+0];
                ov.y = acc[g*4+i][gg*4+1] + bias[c+1];
                ov.z = acc[g*4+i][gg*4+2] + bias[c+2];
                ov.w = acc[g*4+i][gg*4+3] + bias[c+3];
                *(float4*)&out[(size_t)r*CDIM + c] = ov;
            }
        }
}

// ---------------- RoPE (in place on g_q, g_k) --------------------------------
__global__ void rope_kernel(const float* __restrict__ sin_t,
                            const float* __restrict__ cos_t)
{
    int p = blockIdx.x * blockDim.x + threadIdx.x;   // pair index
    if (p >= MTOT * (CDIM/2)) return;
    int m  = p / (CDIM/2);
    int pc = p - m * (CDIM/2);
    int c0 = pc * 2;
    int d0 = c0 & 127;
    int n  = m % NTOK;
    float s0 = sin_t[n*KD + d0],  s1 = sin_t[n*KD + d0 + 1];
    float cc0 = cos_t[n*KD + d0], cc1 = cos_t[n*KD + d0 + 1];

    float2 q = ((float2*)g_q)[p];
    float2 k = ((float2*)g_k)[p];
    float2 qo, ko;
    qo.x = q.x*cc0 + q.y*s0;   qo.y = q.y*cc1 - q.x*s1;
    ko.x = k.x*cc0 + k.y*s0;   ko.y = k.y*cc1 - k.x*s1;
    ((float2*)g_q)[p] = qo;
    ((float2*)g_k)[p] = ko;
}

// ---------------- LePE: 5x5 depthwise conv on v ------------------------------
__global__ void lepe_conv(const float* __restrict__ wgt,
                          const float* __restrict__ bias)
{
    int idx = blockIdx.x * blockDim.x + threadIdx.x;
    if (idx >= MTOT * CDIM) return;
    int c = idx & (CDIM-1);
    int t = idx >> 10;
    int x = t % WW; t /= WW;
    int y = t % HH;
    int b = t / HH;
    float sum = bias[c];
#pragma unroll
    for (int ky = 0; ky < 5; ky++) {
        int yy = y + ky - 2;
        if (yy < 0 || yy >= HH) continue;
#pragma unroll
        for (int kx = 0; kx < 5; kx++) {
            int xx = x + kx - 2;
            if (xx < 0 || xx >= WW) continue;
            sum += g_v[(((size_t)(b*HH) + yy)*WW + xx)*CDIM + c]
                 * wgt[(ky*5 + kx)*CDIM + c];
        }
    }
    g_lepe[idx] = sum;
}

// ---------------- attention: flash-style, fp32 -------------------------------
#define AM 128          // q rows per block
#define AN 64           // k rows per chunk
#define QS_STRIDE 132
#define KS_STRIDE 132
#define PS_STRIDE 68
#define ATTN_SMEM ((AM*QS_STRIDE + 2*AN*KS_STRIDE + AM*PS_STRIDE) * 4)

__global__ __launch_bounds__(256,1) void attn_kernel(const float* __restrict__ mask)
{
    extern __shared__ float sm[];
    float* Qs = sm;                         // [AM][132]
    float* Ks = Qs + AM*QS_STRIDE;          // [AN][132]
    float* Vs = Ks + AN*KS_STRIDE;          // [AN][132]
    float* Ps = Vs + AN*KS_STRIDE;          // [AM][68]

    const int tid = threadIdx.x;
    const int tx = tid & 15, ty = tid >> 4;
    const int qt = blockIdx.x;
    const int bh = blockIdx.y;
    const int b = bh >> 3, h = bh & 7;
    const int qbase = qt * AM;

    {   // Q tile: 128 rows x 128 dims
        const float* qg = g_q + (size_t)(b*NTOK + qbase)*CDIM + h*KD;
#pragma unroll
        for (int i = 0; i < 16; i++) {
            int idx = tid + i*256;
            int r = idx >> 5, d4 = idx & 31;
            *(float4*)&Qs[r*QS_STRIDE + d4*4] = *(const float4*)(qg + (size_t)r*CDIM + d4*4);
        }
    }

    float rmax[8], rsum[8];
    float o[8][8];
#pragma unroll
    for (int i = 0; i < 8; i++) {
        rmax[i] = -1e30f; rsum[i] = 0.f;
#pragma unroll
        for (int j = 0; j < 8; j++) o[i][j] = 0.f;
    }
    const int rb0 = ty*4, rb1 = 64 + ty*4;

    for (int kc = 0; kc < NTOK/AN; kc++) {
        const int kbase = kc * AN;
        __syncthreads();
        {
            const float* kg = g_k + (size_t)(b*NTOK + kbase)*CDIM + h*KD;
            const float* vg = g_v + (size_t)(b*NTOK + kbase)*CDIM + h*KD;
#pragma unroll
            for (int i = 0; i < 8; i++) {
                int idx = tid + i*256;
                int r = idx >> 5, d4 = idx & 31;
                *(float4*)&Ks[r*KS_STRIDE + d4*4] = *(const float4*)(kg + (size_t)r*CDIM + d4*4);
                *(float4*)&Vs[r*KS_STRIDE + d4*4] = *(const float4*)(vg + (size_t)r*CDIM + d4*4);
            }
        }
        __syncthreads();

        float s[8][4];
#pragma unroll
        for (int i = 0; i < 8; i++)
#pragma unroll
            for (int j = 0; j < 4; j++) s[i][j] = 0.f;

#pragma unroll 8
        for (int d4 = 0; d4 < 32; d4++) {
            float4 kk[4];
#pragma unroll
            for (int j = 0; j < 4; j++)
                kk[j] = *(const float4*)&Ks[(j*16 + tx)*KS_STRIDE + d4*4];
#pragma unroll
            for (int g = 0; g < 2; g++) {
                int rb = g ? rb1 : rb0;
#pragma unroll
                for (int i = 0; i < 4; i++) {
                    float4 qq = *(const float4*)&Qs[(rb+i)*QS_STRIDE + d4*4];
#pragma unroll
                    for (int j = 0; j < 4; j++)
                        s[g*4+i][j] += qq.x*kk[j].x + qq.y*kk[j].y
                                     + qq.z*kk[j].z + qq.w*kk[j].w;
                }
            }
        }

        // mask add
#pragma unroll
        for (int g = 0; g < 2; g++) {
            int rb = g ? rb1 : rb0;
#pragma unroll
            for (int i = 0; i < 4; i++) {
                const float* mp = mask + ((size_t)h*NTOK + (qbase + rb + i))*NTOK + kbase + tx;
#pragma unroll
                for (int j = 0; j < 4; j++)
                    s[g*4+i][j] += mp[j*16];
            }
        }

        // online softmax update
#pragma unroll
        for (int ii = 0; ii < 8; ii++) {
            float mx = fmaxf(fmaxf(s[ii][0], s[ii][1]), fmaxf(s[ii][2], s[ii][3]));
#pragma unroll
            for (int w = 1; w < 16; w <<= 1)
                mx = fmaxf(mx, __shfl_xor_sync(0xFFFFFFFFu, mx, w, 16));
            float nm = fmaxf(rmax[ii], mx);
            float corr = __expf(rmax[ii] - nm);
            rmax[ii] = nm;
            float ps = 0.f;
#pragma unroll
            for (int j = 0; j < 4; j++) {
                float p = __expf(s[ii][j] - nm);
                s[ii][j] = p;
                ps += p;
            }
#pragma unroll
            for (int w = 1; w < 16; w <<= 1)
                ps += __shfl_xor_sync(0xFFFFFFFFu, ps, w, 16);
            rsum[ii] = rsum[ii]*corr + ps;
#pragma unroll
            for (int j = 0; j < 8; j++) o[ii][j] *= corr;
        }

        // P to smem
#pragma unroll
        for (int g = 0; g < 2; g++) {
            int rb = g ? rb1 : rb0;
#pragma unroll
            for (int i = 0; i < 4; i++)
#pragma unroll
                for (int j = 0; j < 4; j++)
                    Ps[(rb+i)*PS_STRIDE + j*16 + tx] = s[g*4+i][j];
        }
        __syncthreads();

        // O += P @ V
#pragma unroll 4
        for (int j = 0; j < AN; j++) {
            float4 v0 = *(const float4*)&Vs[j*KS_STRIDE + tx*4];
            float4 v1 = *(const float4*)&Vs[j*KS_STRIDE + 64 + tx*4];
#pragma unroll
            for (int g = 0; g < 2; g++) {
                int rb = g ? rb1 : rb0;
#pragma unroll
                for (int i = 0; i < 4; i++) {
                    float p = Ps[(rb+i)*PS_STRIDE + j];
                    int ii = g*4 + i;
                    o[ii][0] += p*v0.x; o[ii][1] += p*v0.y;
                    o[ii][2] += p*v0.z; o[ii][3] += p*v0.w;
                    o[ii][4] += p*v1.x; o[ii][5] += p*v1.y;
                    o[ii][6] += p*v1.z; o[ii][7] += p*v1.w;
                }
            }
        }
    }

    // epilogue
    float* og = g_attn + (((size_t)(b*NHEADS) + h)*NTOK + qbase)*KD;
#pragma unroll
    for (int g = 0; g < 2; g++) {
        int rb = g ? rb1 : rb0;
#pragma unroll
        for (int i = 0; i < 4; i++) {
            int ii = g*4 + i;
            float inv = 1.f / rsum[ii];
            float4 w0, w1;
            w0.x = o[ii][0]*inv; w0.y = o[ii][1]*inv;
            w0.z = o[ii][2]*inv; w0.w = o[ii][3]*inv;
            w1.x = o[ii][4]*inv; w1.y = o[ii][5]*inv;
            w1.z = o[ii][6]*inv; w1.w = o[ii][7]*inv;
            *(float4*)&og[(size_t)(rb+i)*KD + tx*4]      = w0;
            *(float4*)&og[(size_t)(rb+i)*KD + 64 + tx*4] = w1;
        }
    }
}

// ---------------- launcher ---------------------------------------------------
extern "C" void kernel_launch(void* const* d_in, const int* in_sizes, int n_in,
                              void* d_out, int out_size)
{
    const float* x      = (const float*)d_in[0];
    const float* sin_t  = (const float*)d_in[1];
    const float* cos_t  = (const float*)d_in[2];
    const float* mask   = (const float*)d_in[3];
    const float* Wq     = (const float*)d_in[4];
    const float* bq     = (const float*)d_in[5];
    const float* Wk     = (const float*)d_in[6];
    const float* bk     = (const float*)d_in[7];
    const float* Wv     = (const float*)d_in[8];
    const float* bv     = (const float*)d_in[9];
    const float* lepe_w = (const float*)d_in[10];
    const float* lepe_b = (const float*)d_in[11];
    const float* Wo     = (const float*)d_in[12];
    const float* bo     = (const float*)d_in[13];
    float* out = (float*)d_out;

    const float scaling = 0.08838834764831845f;   // 1/sqrt(128)

    dim3 gg(CDIM/GBN, MTOT/GBM);   // (8, 36)
    gemm_qkv<<<gg, 256>>>(x, Wq, bq, 1.f,     0);
    gemm_qkv<<<gg, 256>>>(x, Wk, bk, scaling, 1);
    gemm_qkv<<<gg, 256>>>(x, Wv, bv, 1.f,     2);

    rope_kernel<<<(MTOT*(CDIM/2) + 255)/256, 256>>>(sin_t, cos_t);
    lepe_conv<<<(MTOT*CDIM + 255)/256, 256>>>(lepe_w, lepe_b);

    cudaFuncSetAttribute(attn_kernel,
                         cudaFuncAttributeMaxDynamicSharedMemorySize, ATTN_SMEM);
    attn_kernel<<<dim3(NTOK/AM, BATCH*NHEADS), 256, ATTN_SMEM>>>(mask);

    gemm_final<<<gg, 256>>>(Wo, bo, out);
}

// round 4
// speedup vs baseline: 1.4525x; 1.4525x over previous
#include <cuda_runtime.h>
#include <cstdint>
#include <math.h>

#define CDIM   1024
#define NHEADS 8
#define KD     128
#define BATCH  2
#define HH     48
#define WW     48
#define NTOK   (HH*WW)        // 2304
#define MTOT   (BATCH*NTOK)   // 4608

// ---------------- scratch (static device memory; no allocations) -------------
__device__ float g_q[MTOT*CDIM];
__device__ float g_k[MTOT*CDIM];
__device__ float g_v[MTOT*CDIM];
__device__ float g_lepe[MTOT*CDIM];
__device__ float g_attn[BATCH*NHEADS*NTOK*KD];

// ====================== tf32 mma.sync GEMM ==================================
// out[m,n] = (sum_k A[m,k]*W[n,k] + bias[n]) * scale
// block tile 128x128, K-chunk 32, double-buffered cp.async, 8 warps (2m x 4n)

#define TKC 32                         // K per smem chunk (floats)
#define SSTR 36                        // smem row stride in words (pad 4)
#define TILE_W (128*SSTR)              // words per tile (A or B)
#define STAGE_W (2*TILE_W)             // A + B
#define GEMM_SMEM (2*STAGE_W*4)        // bytes, 2 stages

__device__ __forceinline__ uint32_t smem_u32(const void* p) {
    uint32_t a;
    asm("{ .reg .u64 t; cvta.to.shared.u64 t, %1; cvt.u32.u64 %0, t; }"
        : "=r"(a) : "l"(p));
    return a;
}
__device__ __forceinline__ void cp16(uint32_t s, const void* g) {
    asm volatile("cp.async.cg.shared.global [%0], [%1], 16;" :: "r"(s), "l"(g));
}
__device__ __forceinline__ uint32_t f2tf32(float f) {
    uint32_t r; asm("cvt.rna.tf32.f32 %0, %1;" : "=r"(r) : "f"(f)); return r;
}
__device__ __forceinline__ void mma_tf32(float* d, const uint32_t* a, const uint32_t* b) {
    asm volatile(
      "mma.sync.aligned.m16n8k8.row.col.f32.tf32.tf32.f32 "
      "{%0,%1,%2,%3}, {%4,%5,%6,%7}, {%8,%9}, {%0,%1,%2,%3};"
      : "+f"(d[0]), "+f"(d[1]), "+f"(d[2]), "+f"(d[3])
      : "r"(a[0]), "r"(a[1]), "r"(a[2]), "r"(a[3]), "r"(b[0]), "r"(b[1]));
}

__device__ __forceinline__ void gemm_prefetch(
        float* sm, int buf, const float* Ag, const float* Bg, int kc, int tid)
{
    float* As = sm + buf * STAGE_W;
    float* Bs = As + TILE_W;
    uint32_t abase = smem_u32(As);
    uint32_t bbase = smem_u32(Bs);
#pragma unroll
    for (int i = 0; i < 4; i++) {
        int idx = tid + i * 256;          // 0..1023
        int row = idx >> 3;
        int c4  = (idx & 7) * 4;
        uint32_t soff = (uint32_t)(row * SSTR + c4) * 4;
        size_t  goff = (size_t)row * CDIM + kc * TKC + c4;
        cp16(abase + soff, Ag + goff);
        cp16(bbase + soff, Bg + goff);
    }
    asm volatile("cp.async.commit_group;");
}

__global__ __launch_bounds__(256,1) void gemm_tc(
        const float* __restrict__ Aarg, int asel,
        const float* __restrict__ W,
        const float* __restrict__ bias,
        float scale, float* __restrict__ extout, int osel)
{
    extern __shared__ float sm[];
    const int tid = threadIdx.x;
    const int wid = tid >> 5, lane = tid & 31;
    const int gid = lane >> 2, tig = lane & 3;
    const int wm = wid & 1, wn = wid >> 1;          // 2 x 4 warp grid
    const int bm = blockIdx.y * 128, bn = blockIdx.x * 128;

    const float* Ag = (asel == 0) ? Aarg : g_q;
    Ag += (size_t)bm * CDIM;
    const float* Bg = W + (size_t)bn * CDIM;
    float* out = (osel == 0) ? g_q : (osel == 1) ? g_k : (osel == 2) ? g_v : extout;

    float acc[4][4][4];
#pragma unroll
    for (int i = 0; i < 4; i++)
#pragma unroll
        for (int j = 0; j < 4; j++)
#pragma unroll
            for (int r = 0; r < 4; r++) acc[i][j][r] = 0.f;

    gemm_prefetch(sm, 0, Ag, Bg, 0, tid);

    const int a_r0 = wm * 64 + gid;       // + mt*16 (+8)
    const int b_r0 = wn * 32 + gid;       // + nt*8

    for (int kc = 0; kc < CDIM / TKC; kc++) {
        const int buf = kc & 1;
        asm volatile("cp.async.wait_group 0;" ::: "memory");
        __syncthreads();
        if (kc + 1 < CDIM / TKC)
            gemm_prefetch(sm, buf ^ 1, Ag, Bg, kc + 1, tid);

        const float* As = sm + buf * STAGE_W;
        const float* Bs = As + TILE_W;

#pragma unroll
        for (int k8 = 0; k8 < TKC / 8; k8++) {
            const int k0 = k8 * 8 + tig;
            uint32_t af[4][4], bf[4][2];
#pragma unroll
            for (int mt = 0; mt < 4; mt++) {
                const float* ap = As + (a_r0 + mt*16) * SSTR + k0;
                af[mt][0] = f2tf32(ap[0]);
                af[mt][1] = f2tf32(ap[8*SSTR]);
                af[mt][2] = f2tf32(ap[4]);
                af[mt][3] = f2tf32(ap[8*SSTR + 4]);
            }
#pragma unroll
            for (int nt = 0; nt < 4; nt++) {
                const float* bp = Bs + (b_r0 + nt*8) * SSTR + k0;
                bf[nt][0] = f2tf32(bp[0]);
                bf[nt][1] = f2tf32(bp[4]);
            }
#pragma unroll
            for (int mt = 0; mt < 4; mt++)
#pragma unroll
                for (int nt = 0; nt < 4; nt++)
                    mma_tf32(acc[mt][nt], af[mt], bf[nt]);
        }
        __syncthreads();
    }

    // epilogue: D rows bm+wm*64+mt*16+gid(+8), cols bn+wn*32+nt*8+tig*2(+1)
#pragma unroll
    for (int mt = 0; mt < 4; mt++) {
        int r0 = bm + wm*64 + mt*16 + gid;
#pragma unroll
        for (int nt = 0; nt < 4; nt++) {
            int c = bn + wn*32 + nt*8 + tig*2;
            float2 bb = *(const float2*)&bias[c];
            float2 o0, o1;
            o0.x = (acc[mt][nt][0] + bb.x) * scale;
            o0.y = (acc[mt][nt][1] + bb.y) * scale;
            o1.x = (acc[mt][nt][2] + bb.x) * scale;
            o1.y = (acc[mt][nt][3] + bb.y) * scale;
            *(float2*)&out[(size_t)r0 * CDIM + c]       = o0;
            *(float2*)&out[(size_t)(r0+8) * CDIM + c]   = o1;
        }
    }
}

// ---------------- fuse: A for final GEMM = attn reorder + lepe (into g_q) ----
__global__ void fuse_add(void)
{
    int i = blockIdx.x * blockDim.x + threadIdx.x;
    if (i >= MTOT * CDIM) return;
    int m = i >> 10, k = i & 1023;
    int b = m / NTOK, n = m - b * NTOK;
    int h = k >> 7,  d = k & 127;
    g_q[i] = g_attn[((((size_t)b * NHEADS) + h) * NTOK + n) * KD + d] + g_lepe[i];
}

// ---------------- RoPE (in place on g_q, g_k) --------------------------------
__global__ void rope_kernel(const float* __restrict__ sin_t,
                            const float* __restrict__ cos_t)
{
    int p = blockIdx.x * blockDim.x + threadIdx.x;   // pair index
    if (p >= MTOT * (CDIM/2)) return;
    int m  = p / (CDIM/2);
    int pc = p - m * (CDIM/2);
    int c0 = pc * 2;
    int d0 = c0 & 127;
    int n  = m % NTOK;
    float s0 = sin_t[n*KD + d0],  s1 = sin_t[n*KD + d0 + 1];
    float cc0 = cos_t[n*KD + d0], cc1 = cos_t[n*KD + d0 + 1];

    float2 q = ((float2*)g_q)[p];
    float2 k = ((float2*)g_k)[p];
    float2 qo, ko;
    qo.x = q.x*cc0 + q.y*s0;   qo.y = q.y*cc1 - q.x*s1;
    ko.x = k.x*cc0 + k.y*s0;   ko.y = k.y*cc1 - k.x*s1;
    ((float2*)g_q)[p] = qo;
    ((float2*)g_k)[p] = ko;
}

// ---------------- LePE: 5x5 depthwise conv on v ------------------------------
__global__ void lepe_conv(const float* __restrict__ wgt,
                          const float* __restrict__ bias)
{
    int idx = blockIdx.x * blockDim.x + threadIdx.x;
    if (idx >= MTOT * CDIM) return;
    int c = idx & (CDIM-1);
    int t = idx >> 10;
    int x = t % WW; t /= WW;
    int y = t % HH;
    int b = t / HH;
    float sum = bias[c];
#pragma unroll
    for (int ky = 0; ky < 5; ky++) {
        int yy = y + ky - 2;
        if (yy < 0 || yy >= HH) continue;
#pragma unroll
        for (int kx = 0; kx < 5; kx++) {
            int xx = x + kx - 2;
            if (xx < 0 || xx >= WW) continue;
            sum += g_v[(((size_t)(b*HH) + yy)*WW + xx)*CDIM + c]
                 * wgt[(ky*5 + kx)*CDIM + c];
        }
    }
    g_lepe[idx] = sum;
}

// ---------------- attention: flash-style, fp32 -------------------------------
#define AM 128          // q rows per block
#define AN 64           // k rows per chunk
#define QS_STRIDE 132
#define KS_STRIDE 132
#define PS_STRIDE 68
#define ATTN_SMEM ((AM*QS_STRIDE + 2*AN*KS_STRIDE + AM*PS_STRIDE) * 4)

__global__ __launch_bounds__(256,1) void attn_kernel(const float* __restrict__ mask)
{
    extern __shared__ float sm[];
    float* Qs = sm;                         // [AM][132]
    float* Ks = Qs + AM*QS_STRIDE;          // [AN][132]
    float* Vs = Ks + AN*KS_STRIDE;          // [AN][132]
    float* Ps = Vs + AN*KS_STRIDE;          // [AM][68]

    const int tid = threadIdx.x;
    const int tx = tid & 15, ty = tid >> 4;
    const int qt = blockIdx.x;
    const int bh = blockIdx.y;
    const int b = bh >> 3, h = bh & 7;
    const int qbase = qt * AM;

    {   // Q tile: 128 rows x 128 dims
        const float* qg = g_q + (size_t)(b*NTOK + qbase)*CDIM + h*KD;
#pragma unroll
        for (int i = 0; i < 16; i++) {
            int idx = tid + i*256;
            int r = idx >> 5, d4 = idx & 31;
            *(float4*)&Qs[r*QS_STRIDE + d4*4] = *(const float4*)(qg + (size_t)r*CDIM + d4*4);
        }
    }

    float rmax[8], rsum[8];
    float o[8][8];
#pragma unroll
    for (int i = 0; i < 8; i++) {
        rmax[i] = -1e30f; rsum[i] = 0.f;
#pragma unroll
        for (int j = 0; j < 8; j++) o[i][j] = 0.f;
    }
    const int rb0 = ty*4, rb1 = 64 + ty*4;

    for (int kc = 0; kc < NTOK/AN; kc++) {
        const int kbase = kc * AN;
        __syncthreads();
        {
            const float* kg = g_k + (size_t)(b*NTOK + kbase)*CDIM + h*KD;
            const float* vg = g_v + (size_t)(b*NTOK + kbase)*CDIM + h*KD;
#pragma unroll
            for (int i = 0; i < 8; i++) {
                int idx = tid + i*256;
                int r = idx >> 5, d4 = idx & 31;
                *(float4*)&Ks[r*KS_STRIDE + d4*4] = *(const float4*)(kg + (size_t)r*CDIM + d4*4);
                *(float4*)&Vs[r*KS_STRIDE + d4*4] = *(const float4*)(vg + (size_t)r*CDIM + d4*4);
            }
        }
        __syncthreads();

        float s[8][4];
#pragma unroll
        for (int i = 0; i < 8; i++)
#pragma unroll
            for (int j = 0; j < 4; j++) s[i][j] = 0.f;

#pragma unroll 8
        for (int d4 = 0; d4 < 32; d4++) {
            float4 kk[4];
#pragma unroll
            for (int j = 0; j < 4; j++)
                kk[j] = *(const float4*)&Ks[(j*16 + tx)*KS_STRIDE + d4*4];
#pragma unroll
            for (int g = 0; g < 2; g++) {
                int rb = g ? rb1 : rb0;
#pragma unroll
                for (int i = 0; i < 4; i++) {
                    float4 qq = *(const float4*)&Qs[(rb+i)*QS_STRIDE + d4*4];
#pragma unroll
                    for (int j = 0; j < 4; j++)
                        s[g*4+i][j] += qq.x*kk[j].x + qq.y*kk[j].y
                                     + qq.z*kk[j].z + qq.w*kk[j].w;
                }
            }
        }

        // mask add
#pragma unroll
        for (int g = 0; g < 2; g++) {
            int rb = g ? rb1 : rb0;
#pragma unroll
            for (int i = 0; i < 4; i++) {
                const float* mp = mask + ((size_t)h*NTOK + (qbase + rb + i))*NTOK + kbase + tx;
#pragma unroll
                for (int j = 0; j < 4; j++)
                    s[g*4+i][j] += mp[j*16];
            }
        }

        // online softmax update
#pragma unroll
        for (int ii = 0; ii < 8; ii++) {
            float mx = fmaxf(fmaxf(s[ii][0], s[ii][1]), fmaxf(s[ii][2], s[ii][3]));
#pragma unroll
            for (int w = 1; w < 16; w <<= 1)
                mx = fmaxf(mx, __shfl_xor_sync(0xFFFFFFFFu, mx, w, 16));
            float nm = fmaxf(rmax[ii], mx);
            float corr = __expf(rmax[ii] - nm);
            rmax[ii] = nm;
            float ps = 0.f;
#pragma unroll
            for (int j = 0; j < 4; j++) {
                float p = __expf(s[ii][j] - nm);
                s[ii][j] = p;
                ps += p;
            }
#pragma unroll
            for (int w = 1; w < 16; w <<= 1)
                ps += __shfl_xor_sync(0xFFFFFFFFu, ps, w, 16);
            rsum[ii] = rsum[ii]*corr + ps;
#pragma unroll
            for (int j = 0; j < 8; j++) o[ii][j] *= corr;
        }

        // P to smem
#pragma unroll
        for (int g = 0; g < 2; g++) {
            int rb = g ? rb1 : rb0;
#pragma unroll
            for (int i = 0; i < 4; i++)
#pragma unroll
                for (int j = 0; j < 4; j++)
                    Ps[(rb+i)*PS_STRIDE + j*16 + tx] = s[g*4+i][j];
        }
        __syncthreads();

        // O += P @ V
#pragma unroll 4
        for (int j = 0; j < AN; j++) {
            float4 v0 = *(const float4*)&Vs[j*KS_STRIDE + tx*4];
            float4 v1 = *(const float4*)&Vs[j*KS_STRIDE + 64 + tx*4];
#pragma unroll
            for (int g = 0; g < 2; g++) {
                int rb = g ? rb1 : rb0;
#pragma unroll
                for (int i = 0; i < 4; i++) {
                    float p = Ps[(rb+i)*PS_STRIDE + j];
                    int ii = g*4 + i;
                    o[ii][0] += p*v0.x; o[ii][1] += p*v0.y;
                    o[ii][2] += p*v0.z; o[ii][3] += p*v0.w;
                    o[ii][4] += p*v1.x; o[ii][5] += p*v1.y;
                    o[ii][6] += p*v1.z; o[ii][7] += p*v1.w;
                }
            }
        }
    }

    // epilogue
    float* og = g_attn + (((size_t)(b*NHEADS) + h)*NTOK + qbase)*KD;
#pragma unroll
    for (int g = 0; g < 2; g++) {
        int rb = g ? rb1 : rb0;
#pragma unroll
        for (int i = 0; i < 4; i++) {
            int ii = g*4 + i;
            float inv = 1.f / rsum[ii];
            float4 w0, w1;
            w0.x = o[ii][0]*inv; w0.y = o[ii][1]*inv;
            w0.z = o[ii][2]*inv; w0.w = o[ii][3]*inv;
            w1.x = o[ii][4]*inv; w1.y = o[ii][5]*inv;
            w1.z = o[ii][6]*inv; w1.w = o[ii][7]*inv;
            *(float4*)&og[(size_t)(rb+i)*KD + tx*4]      = w0;
            *(float4*)&og[(size_t)(rb+i)*KD + 64 + tx*4] = w1;
        }
    }
}

// ---------------- launcher ---------------------------------------------------
extern "C" void kernel_launch(void* const* d_in, const int* in_sizes, int n_in,
                              void* d_out, int out_size)
{
    const float* x      = (const float*)d_in[0];
    const float* sin_t  = (const float*)d_in[1];
    const float* cos_t  = (const float*)d_in[2];
    const float* mask   = (const float*)d_in[3];
    const float* Wq     = (const float*)d_in[4];
    const float* bq     = (const float*)d_in[5];
    const float* Wk     = (const float*)d_in[6];
    const float* bk     = (const float*)d_in[7];
    const float* Wv     = (const float*)d_in[8];
    const float* bv     = (const float*)d_in[9];
    const float* lepe_w = (const float*)d_in[10];
    const float* lepe_b = (const float*)d_in[11];
    const float* Wo     = (const float*)d_in[12];
    const float* bo     = (const float*)d_in[13];
    float* out = (float*)d_out;

    const float scaling = 0.08838834764831845f;   // 1/sqrt(128)

    cudaFuncSetAttribute(gemm_tc,
                         cudaFuncAttributeMaxDynamicSharedMemorySize, GEMM_SMEM);
    dim3 gg(CDIM/128, MTOT/128);   // (8, 36)
    gemm_tc<<<gg, 256, GEMM_SMEM>>>(x, 0, Wq, bq, 1.f,     nullptr, 0);
    gemm_tc<<<gg, 256, GEMM_SMEM>>>(x, 0, Wk, bk, scaling, nullptr, 1);
    gemm_tc<<<gg, 256, GEMM_SMEM>>>(x, 0, Wv, bv, 1.f,     nullptr, 2);

    rope_kernel<<<(MTOT*(CDIM/2) + 255)/256, 256>>>(sin_t, cos_t);
    lepe_conv<<<(MTOT*CDIM + 255)/256, 256>>>(lepe_w, lepe_b);

    cudaFuncSetAttribute(attn_kernel,
                         cudaFuncAttributeMaxDynamicSharedMemorySize, ATTN_SMEM);
    attn_kernel<<<dim3(NTOK/AM, BATCH*NHEADS), 256, ATTN_SMEM>>>(mask);

    fuse_add<<<(MTOT*CDIM + 255)/256, 256>>>();
    gemm_tc<<<gg, 256, GEMM_SMEM>>>(nullptr, 1, Wo, bo, 1.f, out, 3);
}

// round 7
// speedup vs baseline: 2.5224x; 1.7366x over previous
#include <cuda_runtime.h>
#include <cstdint>
#include <math.h>

#define CDIM   1024
#define NHEADS 8
#define KD     128
#define BATCH  2
#define HH     48
#define WW     48
#define NTOK   (HH*WW)        // 2304
#define MTOT   (BATCH*NTOK)   // 4608

// ---------------- scratch (static device memory; no allocations) -------------
__device__ float g_q[MTOT*CDIM];
__device__ float g_k[MTOT*CDIM];
__device__ float g_v[MTOT*CDIM];
__device__ float g_lepe[MTOT*CDIM];
__device__ float g_attn[BATCH*NHEADS*NTOK*KD];

// ====================== common PTX helpers ==================================
__device__ __forceinline__ uint32_t smem_u32(const void* p) {
    uint32_t a;
    asm("{ .reg .u64 t; cvta.to.shared.u64 t, %1; cvt.u32.u64 %0, t; }"
        : "=r"(a) : "l"(p));
    return a;
}
__device__ __forceinline__ void cp16(uint32_t s, const void* g) {
    asm volatile("cp.async.cg.shared.global [%0], [%1], 16;" :: "r"(s), "l"(g));
}
__device__ __forceinline__ uint32_t f2tf32(float f) {
    uint32_t r; asm("cvt.rna.tf32.f32 %0, %1;" : "=r"(r) : "f"(f)); return r;
}
__device__ __forceinline__ void mma_tf32(float* d, const uint32_t* a, const uint32_t* b) {
    asm volatile(
      "mma.sync.aligned.m16n8k8.row.col.f32.tf32.tf32.f32 "
      "{%0,%1,%2,%3}, {%4,%5,%6,%7}, {%8,%9}, {%0,%1,%2,%3};"
      : "+f"(d[0]), "+f"(d[1]), "+f"(d[2]), "+f"(d[3])
      : "r"(a[0]), "r"(a[1]), "r"(a[2]), "r"(a[3]), "r"(b[0]), "r"(b[1]));
}

// ====================== tf32 mma.sync GEMM ==================================
#define TKC 32                         // K per smem chunk (floats)
#define SSTR 36                        // smem row stride in words (pad 4)
#define TILE_W (128*SSTR)              // words per tile (A or B)
#define STAGE_W (2*TILE_W)             // A + B
#define GEMM_SMEM (2*STAGE_W*4)        // bytes, 2 stages

__device__ __forceinline__ void gemm_prefetch(
        float* sm, int buf, const float* Ag, const float* Bg, int kc, int tid)
{
    float* As = sm + buf * STAGE_W;
    float* Bs = As + TILE_W;
    uint32_t abase = smem_u32(As);
    uint32_t bbase = smem_u32(Bs);
#pragma unroll
    for (int i = 0; i < 4; i++) {
        int idx = tid + i * 256;          // 0..1023
        int row = idx >> 3;
        int c4  = (idx & 7) * 4;
        uint32_t soff = (uint32_t)(row * SSTR + c4) * 4;
        size_t  goff = (size_t)row * CDIM + kc * TKC + c4;
        cp16(abase + soff, Ag + goff);
        cp16(bbase + soff, Bg + goff);
    }
    asm volatile("cp.async.commit_group;");
}

__global__ __launch_bounds__(256,1) void gemm_tc(
        const float* __restrict__ Aarg, int asel,
        const float* __restrict__ W,
        const float* __restrict__ bias,
        float scale, float* __restrict__ extout, int osel)
{
    extern __shared__ float sm[];
    const int tid = threadIdx.x;
    const int wid = tid >> 5, lane = tid & 31;
    const int gid = lane >> 2, tig = lane & 3;
    const int wm = wid & 1, wn = wid >> 1;          // 2 x 4 warp grid
    const int bm = blockIdx.y * 128, bn = blockIdx.x * 128;

    const float* Ag = (asel == 0) ? Aarg : g_q;
    Ag += (size_t)bm * CDIM;
    const float* Bg = W + (size_t)bn * CDIM;
    float* out = (osel == 0) ? g_q : (osel == 1) ? g_k : (osel == 2) ? g_v : extout;

    float acc[4][4][4];
#pragma unroll
    for (int i = 0; i < 4; i++)
#pragma unroll
        for (int j = 0; j < 4; j++)
#pragma unroll
            for (int r = 0; r < 4; r++) acc[i][j][r] = 0.f;

    gemm_prefetch(sm, 0, Ag, Bg, 0, tid);

    const int a_r0 = wm * 64 + gid;
    const int b_r0 = wn * 32 + gid;

    for (int kc = 0; kc < CDIM / TKC; kc++) {
        const int buf = kc & 1;
        asm volatile("cp.async.wait_group 0;" ::: "memory");
        __syncthreads();
        if (kc + 1 < CDIM / TKC)
            gemm_prefetch(sm, buf ^ 1, Ag, Bg, kc + 1, tid);

        const float* As = sm + buf * STAGE_W;
        const float* Bs = As + TILE_W;

#pragma unroll
        for (int k8 = 0; k8 < TKC / 8; k8++) {
            const int k0 = k8 * 8 + tig;
            uint32_t af[4][4], bf[4][2];
#pragma unroll
            for (int mt = 0; mt < 4; mt++) {
                const float* ap = As + (a_r0 + mt*16) * SSTR + k0;
                af[mt][0] = f2tf32(ap[0]);
                af[mt][1] = f2tf32(ap[8*SSTR]);
                af[mt][2] = f2tf32(ap[4]);
                af[mt][3] = f2tf32(ap[8*SSTR + 4]);
            }
#pragma unroll
            for (int nt = 0; nt < 4; nt++) {
                const float* bp = Bs + (b_r0 + nt*8) * SSTR + k0;
                bf[nt][0] = f2tf32(bp[0]);
                bf[nt][1] = f2tf32(bp[4]);
            }
#pragma unroll
            for (int mt = 0; mt < 4; mt++)
#pragma unroll
                for (int nt = 0; nt < 4; nt++)
                    mma_tf32(acc[mt][nt], af[mt], bf[nt]);
        }
        __syncthreads();
    }

#pragma unroll
    for (int mt = 0; mt < 4; mt++) {
        int r0 = bm + wm*64 + mt*16 + gid;
#pragma unroll
        for (int nt = 0; nt < 4; nt++) {
            int c = bn + wn*32 + nt*8 + tig*2;
            float2 bb = *(const float2*)&bias[c];
            float2 o0, o1;
            o0.x = (acc[mt][nt][0] + bb.x) * scale;
            o0.y = (acc[mt][nt][1] + bb.y) * scale;
            o1.x = (acc[mt][nt][2] + bb.x) * scale;
            o1.y = (acc[mt][nt][3] + bb.y) * scale;
            *(float2*)&out[(size_t)r0 * CDIM + c]       = o0;
            *(float2*)&out[(size_t)(r0+8) * CDIM + c]   = o1;
        }
    }
}

// ---------------- fuse: A for final GEMM = attn reorder + lepe (into g_q) ----
__global__ void fuse_add(void)
{
    int i = blockIdx.x * blockDim.x + threadIdx.x;
    if (i >= MTOT * CDIM) return;
    int m = i >> 10, k = i & 1023;
    int b = m / NTOK, n = m - b * NTOK;
    int h = k >> 7,  d = k & 127;
    g_q[i] = g_attn[((((size_t)b * NHEADS) + h) * NTOK + n) * KD + d] + g_lepe[i];
}

// ---------------- RoPE (in place on g_q, g_k) --------------------------------
__global__ void rope_kernel(const float* __restrict__ sin_t,
                            const float* __restrict__ cos_t)
{
    int p = blockIdx.x * blockDim.x + threadIdx.x;   // pair index
    if (p >= MTOT * (CDIM/2)) return;
    int m  = p / (CDIM/2);
    int pc = p - m * (CDIM/2);
    int c0 = pc * 2;
    int d0 = c0 & 127;
    int n  = m % NTOK;
    float s0 = sin_t[n*KD + d0],  s1 = sin_t[n*KD + d0 + 1];
    float cc0 = cos_t[n*KD + d0], cc1 = cos_t[n*KD + d0 + 1];

    float2 q = ((float2*)g_q)[p];
    float2 k = ((float2*)g_k)[p];
    float2 qo, ko;
    qo.x = q.x*cc0 + q.y*s0;   qo.y = q.y*cc1 - q.x*s1;
    ko.x = k.x*cc0 + k.y*s0;   ko.y = k.y*cc1 - k.x*s1;
    ((float2*)g_q)[p] = qo;
    ((float2*)g_k)[p] = ko;
}

// ---------------- LePE: 5x5 depthwise conv on v ------------------------------
__global__ void lepe_conv(const float* __restrict__ wgt,
                          const float* __restrict__ bias)
{
    int idx = blockIdx.x * blockDim.x + threadIdx.x;
    if (idx >= MTOT * CDIM) return;
    int c = idx & (CDIM-1);
    int t = idx >> 10;
    int x = t % WW; t /= WW;
    int y = t % HH;
    int b = t / HH;
    float sum = bias[c];
#pragma unroll
    for (int ky = 0; ky < 5; ky++) {
        int yy = y + ky - 2;
        if (yy < 0 || yy >= HH) continue;
#pragma unroll
        for (int kx = 0; kx < 5; kx++) {
            int xx = x + kx - 2;
            if (xx < 0 || xx >= WW) continue;
            sum += g_v[(((size_t)(b*HH) + yy)*WW + xx)*CDIM + c]
                 * wgt[(ky*5 + kx)*CDIM + c];
        }
    }
    g_lepe[idx] = sum;
}

// ---------------- attention: flash-style, tf32 mma ---------------------------
// 8 warps x 16 q-rows = 128 q rows per block; 64-key chunks.
// S = Q K^T via m16n8k8 (B-frag reads K [key][dim] directly).
// O = P V  via m16n8k8 (B-frag reads V [key][dim] directly).
#define AM 128
#define AN 64
#define QST 132         // ≡4 mod 32
#define KST 132         // ≡4 mod 32
#define VST 136         // ≡8 mod 32
#define PST 68          // ≡4 mod 32
#define ATTN_SMEM ((AM*QST + AN*KST + AN*VST + AM*PST) * 4)

__global__ __launch_bounds__(256,1) void attn_kernel(const float* __restrict__ mask)
{
    extern __shared__ float sm[];
    float* Qs = sm;                      // [128][132]
    float* Ks = Qs + AM*QST;             // [64][132]
    float* Vs = Ks + AN*KST;             // [64][136]
    float* Ps = Vs + AN*VST;             // [128][68]

    const int tid = threadIdx.x;
    const int wid = tid >> 5, lane = tid & 31;
    const int gid = lane >> 2, tig = lane & 3;
    const int qt = blockIdx.x;
    const int bh = blockIdx.y;
    const int b = bh >> 3, h = bh & 7;
    const int qbase = qt * AM;
    const int wq0 = wid * 16;            // warp's q-row base within block

    {   // Q tile: 128 rows x 128 dims
        const float* qg = g_q + (size_t)(b*NTOK + qbase)*CDIM + h*KD;
#pragma unroll
        for (int i = 0; i < 16; i++) {
            int idx = tid + i*256;
            int r = idx >> 5, d4 = idx & 31;
            *(float4*)&Qs[r*QST + d4*4] = *(const float4*)(qg + (size_t)r*CDIM + d4*4);
        }
    }

    float rmax[2], rsum[2];
    float o[16][4];                      // O rows {gid, gid+8}, dims nt*8+2tig(+1)
#pragma unroll
    for (int r = 0; r < 2; r++) { rmax[r] = -1e30f; rsum[r] = 0.f; }
#pragma unroll
    for (int nt = 0; nt < 16; nt++)
#pragma unroll
        for (int r = 0; r < 4; r++) o[nt][r] = 0.f;

    const float* mrow0 = mask + ((size_t)h*NTOK + (qbase + wq0 + gid))*NTOK;
    const float* mrow1 = mrow0 + (size_t)8*NTOK;

    for (int kc = 0; kc < NTOK/AN; kc++) {
        const int kbase = kc * AN;
        __syncthreads();
        {
            const float* kg = g_k + (size_t)(b*NTOK + kbase)*CDIM + h*KD;
            const float* vg = g_v + (size_t)(b*NTOK + kbase)*CDIM + h*KD;
#pragma unroll
            for (int i = 0; i < 8; i++) {
                int idx = tid + i*256;
                int r = idx >> 5, d4 = idx & 31;
                *(float4*)&Ks[r*KST + d4*4] = *(const float4*)(kg + (size_t)r*CDIM + d4*4);
                *(float4*)&Vs[r*VST + d4*4] = *(const float4*)(vg + (size_t)r*CDIM + d4*4);
            }
        }
        __syncthreads();

        // ---- S = Q K^T  (warp: 16 q x 64 keys = 8 n-tiles) ----
        float s[8][4];
#pragma unroll
        for (int nt = 0; nt < 8; nt++)
#pragma unroll
            for (int r = 0; r < 4; r++) s[nt][r] = 0.f;

#pragma unroll
        for (int k8 = 0; k8 < 16; k8++) {
            const float* ap = Qs + (wq0 + gid)*QST + k8*8 + tig;
            uint32_t af[4];
            af[0] = f2tf32(ap[0]);
            af[1] = f2tf32(ap[8*QST]);
            af[2] = f2tf32(ap[4]);
            af[3] = f2tf32(ap[8*QST + 4]);
#pragma unroll
            for (int nt = 0; nt < 8; nt++) {
                const float* bp = Ks + (nt*8 + gid)*KST + k8*8 + tig;
                uint32_t bf[2];
                bf[0] = f2tf32(bp[0]);
                bf[1] = f2tf32(bp[4]);
                mma_tf32(s[nt], af, bf);
            }
        }

        // ---- mask add ----
#pragma unroll
        for (int nt = 0; nt < 8; nt++) {
            int c = kbase + nt*8 + tig*2;
            float2 m0 = *(const float2*)(mrow0 + c);
            float2 m1 = *(const float2*)(mrow1 + c);
            s[nt][0] += m0.x; s[nt][1] += m0.y;
            s[nt][2] += m1.x; s[nt][3] += m1.y;
        }

        // ---- online softmax (rows gid and gid+8; quad-wide reduce) ----
#pragma unroll
        for (int r = 0; r < 2; r++) {
            float mx = -1e30f;
#pragma unroll
            for (int nt = 0; nt < 8; nt++)
                mx = fmaxf(mx, fmaxf(s[nt][2*r], s[nt][2*r+1]));
            mx = fmaxf(mx, __shfl_xor_sync(0xFFFFFFFFu, mx, 1, 4));
            mx = fmaxf(mx, __shfl_xor_sync(0xFFFFFFFFu, mx, 2, 4));
            float nm = fmaxf(rmax[r], mx);
            float corr = __expf(rmax[r] - nm);
            rmax[r] = nm;
            float ps = 0.f;
#pragma unroll
            for (int nt = 0; nt < 8; nt++) {
                float p0 = __expf(s[nt][2*r]   - nm);
                float p1 = __expf(s[nt][2*r+1] - nm);
                s[nt][2*r] = p0; s[nt][2*r+1] = p1;
                ps += p0 + p1;
            }
            ps += __shfl_xor_sync(0xFFFFFFFFu, ps, 1, 4);
            ps += __shfl_xor_sync(0xFFFFFFFFu, ps, 2, 4);
            rsum[r] = rsum[r]*corr + ps;
#pragma unroll
            for (int nt = 0; nt < 16; nt++) {
                o[nt][2*r]   *= corr;
                o[nt][2*r+1] *= corr;
            }
        }

        // ---- P -> smem (warp-private region) ----
#pragma unroll
        for (int nt = 0; nt < 8; nt++) {
            int c = nt*8 + tig*2;
            *(float2*)&Ps[(wq0 + gid)*PST + c]     = make_float2(s[nt][0], s[nt][1]);
            *(float2*)&Ps[(wq0 + gid + 8)*PST + c] = make_float2(s[nt][2], s[nt][3]);
        }
        __syncwarp();

        // ---- O += P V  (warp: 16 q x 128 dims = 16 n-tiles, 8 k8 steps) ----
#pragma unroll
        for (int k8 = 0; k8 < 8; k8++) {
            const float* ap = Ps + (wq0 + gid)*PST + k8*8 + tig;
            uint32_t af[4];
            af[0] = f2tf32(ap[0]);
            af[1] = f2tf32(ap[8*PST]);
            af[2] = f2tf32(ap[4]);
            af[3] = f2tf32(ap[8*PST + 4]);
#pragma unroll
            for (int nt = 0; nt < 16; nt++) {
                const float* bp = Vs + (k8*8 + tig)*VST + nt*8 + gid;
                uint32_t bf[2];
                bf[0] = f2tf32(bp[0]);
                bf[1] = f2tf32(bp[4*VST]);
                mma_tf32(o[nt], af, bf);
            }
        }
        __syncwarp();
    }

    // ---- epilogue: normalize + store ----
    float* og = g_attn + (((size_t)(b*NHEADS) + h)*NTOK + qbase + wq0)*KD;
#pragma unroll
    for (int r = 0; r < 2; r++) {
        float inv = 1.f / rsum[r];
        float* orow = og + (size_t)(gid + 8*r)*KD;
#pragma unroll
        for (int nt = 0; nt < 16; nt++) {
            float2 w;
            w.x = o[nt][2*r]   * inv;
            w.y = o[nt][2*r+1] * inv;
            *(float2*)&orow[nt*8 + tig*2] = w;
        }
    }
}

// ---------------- launcher ---------------------------------------------------
extern "C" void kernel_launch(void* const* d_in, const int* in_sizes, int n_in,
                              void* d_out, int out_size)
{
    const float* x      = (const float*)d_in[0];
    const float* sin_t  = (const float*)d_in[1];
    const float* cos_t  = (const float*)d_in[2];
    const float* mask   = (const float*)d_in[3];
    const float* Wq     = (const float*)d_in[4];
    const float* bq     = (const float*)d_in[5];
    const float* Wk     = (const float*)d_in[6];
    const float* bk     = (const float*)d_in[7];
    const float* Wv     = (const float*)d_in[8];
    const float* bv     = (const float*)d_in[9];
    const float* lepe_w = (const float*)d_in[10];
    const float* lepe_b = (const float*)d_in[11];
    const float* Wo     = (const float*)d_in[12];
    const float* bo     = (const float*)d_in[13];
    float* out = (float*)d_out;

    const float scaling = 0.08838834764831845f;   // 1/sqrt(128)

    cudaFuncSetAttribute(gemm_tc,
                         cudaFuncAttributeMaxDynamicSharedMemorySize, GEMM_SMEM);
    dim3 gg(CDIM/128, MTOT/128);   // (8, 36)
    gemm_tc<<<gg, 256, GEMM_SMEM>>>(x, 0, Wq, bq, 1.f,     nullptr, 0);
    gemm_tc<<<gg, 256, GEMM_SMEM>>>(x, 0, Wk, bk, scaling, nullptr, 1);
    gemm_tc<<<gg, 256, GEMM_SMEM>>>(x, 0, Wv, bv, 1.f,     nullptr, 2);

    rope_kernel<<<(MTOT*(CDIM/2) + 255)/256, 256>>>(sin_t, cos_t);
    lepe_conv<<<(MTOT*CDIM + 255)/256, 256>>>(lepe_w, lepe_b);

    cudaFuncSetAttribute(attn_kernel,
                         cudaFuncAttributeMaxDynamicSharedMemorySize, ATTN_SMEM);
    attn_kernel<<<dim3(NTOK/AM, BATCH*NHEADS), 256, ATTN_SMEM>>>(mask);

    fuse_add<<<(MTOT*CDIM + 255)/256, 256>>>();
    gemm_tc<<<gg, 256, GEMM_SMEM>>>(nullptr, 1, Wo, bo, 1.f, out, 3);
}

// round 8
// speedup vs baseline: 2.8926x; 1.1468x over previous
#include <cuda_runtime.h>
#include <cstdint>
#include <math.h>

#define CDIM   1024
#define NHEADS 8
#define KD     128
#define BATCH  2
#define HH     48
#define WW     48
#define NTOK   (HH*WW)        // 2304
#define MTOT   (BATCH*NTOK)   // 4608

// ---------------- scratch (static device memory; no allocations) -------------
__device__ float g_q[MTOT*CDIM];
__device__ float g_k[MTOT*CDIM];
__device__ float g_v[MTOT*CDIM];
__device__ float g_vr[MTOT*CDIM];          // tf32-rounded v for attention
__device__ float g_lepe[MTOT*CDIM];
__device__ float g_attn[BATCH*NHEADS*NTOK*KD];   // also: rounded x before attn
__device__ float g_wr[4*CDIM*CDIM];        // tf32-rounded weights

// ====================== common PTX helpers ==================================
__device__ __forceinline__ uint32_t smem_u32(const void* p) {
    uint32_t a;
    asm("{ .reg .u64 t; cvta.to.shared.u64 t, %1; cvt.u32.u64 %0, t; }"
        : "=r"(a) : "l"(p));
    return a;
}
__device__ __forceinline__ void cp16(uint32_t s, const void* g) {
    asm volatile("cp.async.cg.shared.global [%0], [%1], 16;" :: "r"(s), "l"(g));
}
__device__ __forceinline__ uint32_t f2tf32(float f) {
    uint32_t r; asm("cvt.rna.tf32.f32 %0, %1;" : "=r"(r) : "f"(f)); return r;
}
__device__ __forceinline__ float roundtf(float f) {
    return __uint_as_float(f2tf32(f));
}
__device__ __forceinline__ void mma_tf32(float* d, const uint32_t* a, const uint32_t* b) {
    asm volatile(
      "mma.sync.aligned.m16n8k8.row.col.f32.tf32.tf32.f32 "
      "{%0,%1,%2,%3}, {%4,%5,%6,%7}, {%8,%9}, {%0,%1,%2,%3};"
      : "+f"(d[0]), "+f"(d[1]), "+f"(d[2]), "+f"(d[3])
      : "r"(a[0]), "r"(a[1]), "r"(a[2]), "r"(a[3]), "r"(b[0]), "r"(b[1]));
}

// ---------------- pre-round: fp32 -> tf32-in-fp32 ----------------------------
__global__ void round_x(const float* __restrict__ in, float* __restrict__ outp, int n)
{
    int i = blockIdx.x * blockDim.x + threadIdx.x;
    if (i < n) outp[i] = roundtf(in[i]);
}
__global__ void round_w(const float* __restrict__ w0, const float* __restrict__ w1,
                        const float* __restrict__ w2, const float* __restrict__ w3)
{
    int i = blockIdx.x * blockDim.x + threadIdx.x;
    if (i >= CDIM*CDIM) return;
    g_wr[i]               = roundtf(w0[i]);
    g_wr[i +   CDIM*CDIM] = roundtf(w1[i]);
    g_wr[i + 2*CDIM*CDIM] = roundtf(w2[i]);
    g_wr[i + 3*CDIM*CDIM] = roundtf(w3[i]);
}

// ====================== tf32 mma.sync GEMM ==================================
// operands pre-rounded to tf32 -> no cvt in inner loop
#define TKC 32
#define SSTR 36
#define TILE_W (128*SSTR)
#define STAGE_W (2*TILE_W)
#define GEMM_SMEM (2*STAGE_W*4)

__device__ __forceinline__ void gemm_prefetch(
        float* sm, int buf, const float* Ag, const float* Bg, int kc, int tid)
{
    float* As = sm + buf * STAGE_W;
    float* Bs = As + TILE_W;
    uint32_t abase = smem_u32(As);
    uint32_t bbase = smem_u32(Bs);
#pragma unroll
    for (int i = 0; i < 4; i++) {
        int idx = tid + i * 256;
        int row = idx >> 3;
        int c4  = (idx & 7) * 4;
        uint32_t soff = (uint32_t)(row * SSTR + c4) * 4;
        size_t  goff = (size_t)row * CDIM + kc * TKC + c4;
        cp16(abase + soff, Ag + goff);
        cp16(bbase + soff, Bg + goff);
    }
    asm volatile("cp.async.commit_group;");
}

__global__ __launch_bounds__(256,1) void gemm_tc(
        int asel, int wsel,
        const float* __restrict__ bias,
        float scale, float* __restrict__ extout, int osel)
{
    extern __shared__ float sm[];
    const int tid = threadIdx.x;
    const int wid = tid >> 5, lane = tid & 31;
    const int gid = lane >> 2, tig = lane & 3;
    const int wm = wid & 1, wn = wid >> 1;
    const int bm = blockIdx.y * 128, bn = blockIdx.x * 128;

    const float* Ag = ((asel == 0) ? g_attn : g_q) + (size_t)bm * CDIM;
    const float* Bg = g_wr + (size_t)wsel * CDIM * CDIM + (size_t)bn * CDIM;
    float* out = (osel == 0) ? g_q : (osel == 1) ? g_k : (osel == 2) ? g_v : extout;

    float acc[4][4][4];
#pragma unroll
    for (int i = 0; i < 4; i++)
#pragma unroll
        for (int j = 0; j < 4; j++)
#pragma unroll
            for (int r = 0; r < 4; r++) acc[i][j][r] = 0.f;

    gemm_prefetch(sm, 0, Ag, Bg, 0, tid);

    const int a_r0 = wm * 64 + gid;
    const int b_r0 = wn * 32 + gid;

    for (int kc = 0; kc < CDIM / TKC; kc++) {
        const int buf = kc & 1;
        asm volatile("cp.async.wait_group 0;" ::: "memory");
        __syncthreads();
        if (kc + 1 < CDIM / TKC)
            gemm_prefetch(sm, buf ^ 1, Ag, Bg, kc + 1, tid);

        const float* As = sm + buf * STAGE_W;
        const float* Bs = As + TILE_W;

#pragma unroll
        for (int k8 = 0; k8 < TKC / 8; k8++) {
            const int k0 = k8 * 8 + tig;
            uint32_t af[4][4], bf[4][2];
#pragma unroll
            for (int mt = 0; mt < 4; mt++) {
                const float* ap = As + (a_r0 + mt*16) * SSTR + k0;
                af[mt][0] = __float_as_uint(ap[0]);
                af[mt][1] = __float_as_uint(ap[8*SSTR]);
                af[mt][2] = __float_as_uint(ap[4]);
                af[mt][3] = __float_as_uint(ap[8*SSTR + 4]);
            }
#pragma unroll
            for (int nt = 0; nt < 4; nt++) {
                const float* bp = Bs + (b_r0 + nt*8) * SSTR + k0;
                bf[nt][0] = __float_as_uint(bp[0]);
                bf[nt][1] = __float_as_uint(bp[4]);
            }
#pragma unroll
            for (int mt = 0; mt < 4; mt++)
#pragma unroll
                for (int nt = 0; nt < 4; nt++)
                    mma_tf32(acc[mt][nt], af[mt], bf[nt]);
        }
        __syncthreads();
    }

#pragma unroll
    for (int mt = 0; mt < 4; mt++) {
        int r0 = bm + wm*64 + mt*16 + gid;
#pragma unroll
        for (int nt = 0; nt < 4; nt++) {
            int c = bn + wn*32 + nt*8 + tig*2;
            float2 bb = *(const float2*)&bias[c];
            float2 o0, o1;
            o0.x = (acc[mt][nt][0] + bb.x) * scale;
            o0.y = (acc[mt][nt][1] + bb.y) * scale;
            o1.x = (acc[mt][nt][2] + bb.x) * scale;
            o1.y = (acc[mt][nt][3] + bb.y) * scale;
            *(float2*)&out[(size_t)r0 * CDIM + c]       = o0;
            *(float2*)&out[(size_t)(r0+8) * CDIM + c]   = o1;
        }
    }
}

// ---------------- fuse: A for final GEMM (rounded) into g_q ------------------
__global__ void fuse_add(void)
{
    int i = blockIdx.x * blockDim.x + threadIdx.x;
    if (i >= MTOT * CDIM) return;
    int m = i >> 10, k = i & 1023;
    int b = m / NTOK, n = m - b * NTOK;
    int h = k >> 7,  d = k & 127;
    g_q[i] = roundtf(g_attn[((((size_t)b * NHEADS) + h) * NTOK + n) * KD + d]
                     + g_lepe[i]);
}

// ---------------- RoPE (in place on g_q, g_k; writes tf32-rounded) -----------
__global__ void rope_kernel(const float* __restrict__ sin_t,
                            const float* __restrict__ cos_t)
{
    int p = blockIdx.x * blockDim.x + threadIdx.x;
    if (p >= MTOT * (CDIM/2)) return;
    int m  = p / (CDIM/2);
    int pc = p - m * (CDIM/2);
    int c0 = pc * 2;
    int d0 = c0 & 127;
    int n  = m % NTOK;
    float s0 = sin_t[n*KD + d0],  s1 = sin_t[n*KD + d0 + 1];
    float cc0 = cos_t[n*KD + d0], cc1 = cos_t[n*KD + d0 + 1];

    float2 q = ((float2*)g_q)[p];
    float2 k = ((float2*)g_k)[p];
    float2 qo, ko;
    qo.x = roundtf(q.x*cc0 + q.y*s0);   qo.y = roundtf(q.y*cc1 - q.x*s1);
    ko.x = roundtf(k.x*cc0 + k.y*s0);   ko.y = roundtf(k.y*cc1 - k.x*s1);
    ((float2*)g_q)[p] = qo;
    ((float2*)g_k)[p] = ko;
}

// ---------------- LePE conv; also emits rounded v ----------------------------
__global__ void lepe_conv(const float* __restrict__ wgt,
                          const float* __restrict__ bias)
{
    int idx = blockIdx.x * blockDim.x + threadIdx.x;
    if (idx >= MTOT * CDIM) return;
    int c = idx & (CDIM-1);
    int t = idx >> 10;
    int x = t % WW; t /= WW;
    int y = t % HH;
    int b = t / HH;
    float sum = bias[c];
#pragma unroll
    for (int ky = 0; ky < 5; ky++) {
        int yy = y + ky - 2;
        if (yy < 0 || yy >= HH) continue;
#pragma unroll
        for (int kx = 0; kx < 5; kx++) {
            int xx = x + kx - 2;
            if (xx < 0 || xx >= WW) continue;
            sum += g_v[(((size_t)(b*HH) + yy)*WW + xx)*CDIM + c]
                 * wgt[(ky*5 + kx)*CDIM + c];
        }
    }
    g_lepe[idx] = sum;
    g_vr[idx] = roundtf(g_v[idx]);
}

// ---------------- attention: tf32 mma, cp.async double-buffered --------------
// 8 warps x 16 q-rows; 64-key chunks; Q fragments in registers.
#define AM 128
#define AN 64
#define KST 132         // ≡4 mod 32
#define VST 136         // ≡8 mod 32
#define PST 68          // ≡4 mod 32
#define QST 132
#define STW (AN*KST + AN*VST)                 // words per K/V stage (17152)
#define ATTN_SMEM ((2*STW + AM*PST) * 4)      // 172,032 B

__device__ __forceinline__ void attn_prefetch(
        float* sm, int buf, const float* kg, const float* vg, int tid)
{
    uint32_t kb = smem_u32(sm) + (uint32_t)(buf * STW) * 4;
    uint32_t vb = kb + AN*KST*4;
#pragma unroll
    for (int i = 0; i < 8; i++) {
        int idx = tid + i * 256;      // 0..2047
        int r = idx >> 5, d4 = idx & 31;
        cp16(kb + (uint32_t)(r*KST + d4*4)*4, kg + (size_t)r*CDIM + d4*4);
        cp16(vb + (uint32_t)(r*VST + d4*4)*4, vg + (size_t)r*CDIM + d4*4);
    }
    asm volatile("cp.async.commit_group;");
}

__global__ __launch_bounds__(256,1) void attn_kernel(const float* __restrict__ mask)
{
    extern __shared__ float sm[];
    float* Ps = sm + 2*STW;

    const int tid = threadIdx.x;
    const int wid = tid >> 5, lane = tid & 31;
    const int gid = lane >> 2, tig = lane & 3;
    const int qt = blockIdx.x;
    const int bh = blockIdx.y;
    const int b = bh >> 3, h = bh & 7;
    const int qbase = qt * AM;
    const int wq0 = wid * 16;

    // ---- stage Q through smem (stage-0 region), hoist fragments to regs ----
    {
        const float* qg = g_q + (size_t)(b*NTOK + qbase)*CDIM + h*KD;
#pragma unroll
        for (int i = 0; i < 16; i++) {
            int idx = tid + i*256;
            int r = idx >> 5, d4 = idx & 31;
            *(float4*)&sm[r*QST + d4*4] = *(const float4*)(qg + (size_t)r*CDIM + d4*4);
        }
    }
    __syncthreads();
    uint32_t qf[16][4];
#pragma unroll
    for (int k8 = 0; k8 < 16; k8++) {
        const float* ap = sm + (wq0 + gid)*QST + k8*8 + tig;
        qf[k8][0] = __float_as_uint(ap[0]);
        qf[k8][1] = __float_as_uint(ap[8*QST]);
        qf[k8][2] = __float_as_uint(ap[4]);
        qf[k8][3] = __float_as_uint(ap[8*QST + 4]);
    }
    __syncthreads();

    const float* kg0 = g_k  + (size_t)(b*NTOK)*CDIM + h*KD;
    const float* vg0 = g_vr + (size_t)(b*NTOK)*CDIM + h*KD;
    attn_prefetch(sm, 0, kg0, vg0, tid);

    float rmax[2], rsum[2];
    float o[16][4];
#pragma unroll
    for (int r = 0; r < 2; r++) { rmax[r] = -1e30f; rsum[r] = 0.f; }
#pragma unroll
    for (int nt = 0; nt < 16; nt++)
#pragma unroll
        for (int r = 0; r < 4; r++) o[nt][r] = 0.f;

    const float* mrow0 = mask + ((size_t)h*NTOK + (qbase + wq0 + gid))*NTOK;
    const float* mrow1 = mrow0 + (size_t)8*NTOK;

    for (int kc = 0; kc < NTOK/AN; kc++) {
        const int kbase = kc * AN;
        const int buf = kc & 1;
        asm volatile("cp.async.wait_group 0;" ::: "memory");
        __syncthreads();
        if (kc + 1 < NTOK/AN)
            attn_prefetch(sm, buf ^ 1,
                          kg0 + (size_t)(kbase + AN)*CDIM,
                          vg0 + (size_t)(kbase + AN)*CDIM, tid);

        const float* Ks = sm + buf*STW;
        const float* Vs = Ks + AN*KST;

        // ---- S = Q K^T ----
        float s[8][4];
#pragma unroll
        for (int nt = 0; nt < 8; nt++)
#pragma unroll
            for (int r = 0; r < 4; r++) s[nt][r] = 0.f;

#pragma unroll
        for (int k8 = 0; k8 < 16; k8++) {
#pragma unroll
            for (int nt = 0; nt < 8; nt++) {
                const float* bp = Ks + (nt*8 + gid)*KST + k8*8 + tig;
                uint32_t bf[2];
                bf[0] = __float_as_uint(bp[0]);
                bf[1] = __float_as_uint(bp[4]);
                mma_tf32(s[nt], qf[k8], bf);
            }
        }

        // ---- mask add ----
#pragma unroll
        for (int nt = 0; nt < 8; nt++) {
            int c = kbase + nt*8 + tig*2;
            float2 m0 = *(const float2*)(mrow0 + c);
            float2 m1 = *(const float2*)(mrow1 + c);
            s[nt][0] += m0.x; s[nt][1] += m0.y;
            s[nt][2] += m1.x; s[nt][3] += m1.y;
        }

        // ---- online softmax ----
#pragma unroll
        for (int r = 0; r < 2; r++) {
            float mx = -1e30f;
#pragma unroll
            for (int nt = 0; nt < 8; nt++)
                mx = fmaxf(mx, fmaxf(s[nt][2*r], s[nt][2*r+1]));
            mx = fmaxf(mx, __shfl_xor_sync(0xFFFFFFFFu, mx, 1, 4));
            mx = fmaxf(mx, __shfl_xor_sync(0xFFFFFFFFu, mx, 2, 4));
            float nm = fmaxf(rmax[r], mx);
            float corr = __expf(rmax[r] - nm);
            rmax[r] = nm;
            float ps = 0.f;
#pragma unroll
            for (int nt = 0; nt < 8; nt++) {
                float p0 = __expf(s[nt][2*r]   - nm);
                float p1 = __expf(s[nt][2*r+1] - nm);
                s[nt][2*r] = p0; s[nt][2*r+1] = p1;
                ps += p0 + p1;
            }
            ps += __shfl_xor_sync(0xFFFFFFFFu, ps, 1, 4);
            ps += __shfl_xor_sync(0xFFFFFFFFu, ps, 2, 4);
            rsum[r] = rsum[r]*corr + ps;
#pragma unroll
            for (int nt = 0; nt < 16; nt++) {
                o[nt][2*r]   *= corr;
                o[nt][2*r+1] *= corr;
            }
        }

        // ---- P -> smem, rounded to tf32 ----
#pragma unroll
        for (int nt = 0; nt < 8; nt++) {
            int c = nt*8 + tig*2;
            *(float2*)&Ps[(wq0 + gid)*PST + c] =
                make_float2(roundtf(s[nt][0]), roundtf(s[nt][1]));
            *(float2*)&Ps[(wq0 + gid + 8)*PST + c] =
                make_float2(roundtf(s[nt][2]), roundtf(s[nt][3]));
        }
        __syncwarp();

        // ---- O += P V ----
#pragma unroll
        for (int k8 = 0; k8 < 8; k8++) {
            const float* ap = Ps + (wq0 + gid)*PST + k8*8 + tig;
            uint32_t af[4];
            af[0] = __float_as_uint(ap[0]);
            af[1] = __float_as_uint(ap[8*PST]);
            af[2] = __float_as_uint(ap[4]);
            af[3] = __float_as_uint(ap[8*PST + 4]);
#pragma unroll
            for (int nt = 0; nt < 16; nt++) {
                const float* bp = Vs + (k8*8 + tig)*VST + nt*8 + gid;
                uint32_t bf[2];
                bf[0] = __float_as_uint(bp[0]);
                bf[1] = __float_as_uint(bp[4*VST]);
                mma_tf32(o[nt], af, bf);
            }
        }
        __syncwarp();
    }

    // ---- epilogue ----
    float* og = g_attn + (((size_t)(b*NHEADS) + h)*NTOK + qbase + wq0)*KD;
#pragma unroll
    for (int r = 0; r < 2; r++) {
        float inv = 1.f / rsum[r];
        float* orow = og + (size_t)(gid + 8*r)*KD;
#pragma unroll
        for (int nt = 0; nt < 16; nt++) {
            float2 w;
            w.x = o[nt][2*r]   * inv;
            w.y = o[nt][2*r+1] * inv;
            *(float2*)&orow[nt*8 + tig*2] = w;
        }
    }
}

// ---------------- launcher ---------------------------------------------------
extern "C" void kernel_launch(void* const* d_in, const int* in_sizes, int n_in,
                              void* d_out, int out_size)
{
    const float* x      = (const float*)d_in[0];
    const float* sin_t  = (const float*)d_in[1];
    const float* cos_t  = (const float*)d_in[2];
    const float* mask   = (const float*)d_in[3];
    const float* Wq     = (const float*)d_in[4];
    const float* bq     = (const float*)d_in[5];
    const float* Wk     = (const float*)d_in[6];
    const float* bk     = (const float*)d_in[7];
    const float* Wv     = (const float*)d_in[8];
    const float* bv     = (const float*)d_in[9];
    const float* lepe_w = (const float*)d_in[10];
    const float* lepe_b = (const float*)d_in[11];
    const float* Wo     = (const float*)d_in[12];
    const float* bo     = (const float*)d_in[13];
    float* out = (float*)d_out;

    const float scaling = 0.08838834764831845f;   // 1/sqrt(128)

    const int nx = MTOT * CDIM;
    float* g_attn_p;  cudaGetSymbolAddress((void**)&g_attn_p, g_attn);
    round_x<<<(nx + 511)/512, 512>>>(x, g_attn_p, nx);
    round_w<<<(CDIM*CDIM + 511)/512, 512>>>(Wq, Wk, Wv, Wo);

    cudaFuncSetAttribute(gemm_tc,
                         cudaFuncAttributeMaxDynamicSharedMemorySize, GEMM_SMEM);
    dim3 gg(CDIM/128, MTOT/128);   // (8, 36)
    gemm_tc<<<gg, 256, GEMM_SMEM>>>(0, 0, bq, 1.f,     nullptr, 0);
    gemm_tc<<<gg, 256, GEMM_SMEM>>>(0, 1, bk, scaling, nullptr, 1);
    gemm_tc<<<gg, 256, GEMM_SMEM>>>(0, 2, bv, 1.f,     nullptr, 2);

    rope_kernel<<<(MTOT*(CDIM/2) + 255)/256, 256>>>(sin_t, cos_t);
    lepe_conv<<<(nx + 255)/256, 256>>>(lepe_w, lepe_b);

    cudaFuncSetAttribute(attn_kernel,
                         cudaFuncAttributeMaxDynamicSharedMemorySize, ATTN_SMEM);
    attn_kernel<<<dim3(NTOK/AM, BATCH*NHEADS), 256, ATTN_SMEM>>>(mask);

    fuse_add<<<(nx + 255)/256, 256>>>();
    gemm_tc<<<gg, 256, GEMM_SMEM>>>(1, 3, bo, 1.f, out, 3);
}